// round 11
// baseline (speedup 1.0000x reference)
#include <cuda_runtime.h>
#include <cstdint>

// TranslateCube: out(y,x) = bilinear(in, y - ty, x - tx), zero fill.
// [B*T, 256, 256] fp32; (tx, ty) constant per image.
//
// R6-R10 lesson: the LDG-through-registers path caps at ~5.4 TB/s because
// outstanding DRAM bytes are register-file-limited (occ x MLP conserved).
// This round: TMA. Each block stages its 17 input rows (17KB) into SMEM with
// ONE cp.async.bulk + mbarrier (zero register payload, deep HW queue), then
// computes from SMEM via conflict-free LDS.128. Latency hidden by 5-6
// resident blocks per SM overlapping TMA waits with compute.

#define HH 256
#define WW 256
#define PX 8
#define TPR (WW / PX)        // 32 threads per row
#define WPB 8                // warps per block
#define RPT 2                // rows per thread
#define RPB (WPB * RPT)      // 16 output rows per block
#define SROWS (RPB + 1)      // 17 staged input rows

__device__ __forceinline__ uint32_t smem_u32(const void* p) {
    return (uint32_t)__cvta_generic_to_shared(p);
}

__device__ __forceinline__ void mbar_wait_parity0(uint32_t mb) {
    asm volatile(
        "{\n\t"
        ".reg .pred P;\n\t"
        "WAIT_%=:\n\t"
        "mbarrier.try_wait.parity.shared::cta.b64 P, [%0], 0;\n\t"
        "@!P bra WAIT_%=;\n\t"
        "}" :: "r"(mb) : "memory");
}

template <int M>
__device__ __forceinline__ void run_rows(
    const float* __restrict__ sdata, float4* __restrict__ obase,
    int yBase, int c, int qa, int qb, int qc,
    int lo, int hi, int y0_min,
    const float* __restrict__ u0, const float* __restrict__ u1, float ty)
{
#pragma unroll
    for (int r = 0; r < RPT; ++r) {
        const int y = yBase + r;
        const float sy  = (float)y - ty;
        const float y0f = floorf(sy);
        const float wy  = sy - y0f;
        const int   y0  = (int)y0f;
        const float wtop = ((unsigned)y0       < (unsigned)HH) ? (1.0f - wy) : 0.0f;
        const float wbot = ((unsigned)(y0 + 1) < (unsigned)HH) ? wy          : 0.0f;
        // SMEM row indices, clamped INTO the loaded span (valid rows always
        // fall inside it; only zero-weight rows get redirected).
        const int i0 = min(max(y0     - y0_min, lo), hi);
        const int i1 = min(max(y0 + 1 - y0_min, lo), hi);

        const float4* r0 = (const float4*)(sdata + i0 * WW);
        const float4* r1 = (const float4*)(sdata + i1 * WW);

        const float4 A0 = r0[qa], A1 = r0[qb], A2 = r0[qc];
        const float4 B0 = r1[qa], B1 = r1[qb], B2 = r1[qc];

        const float va[12] = {A0.x, A0.y, A0.z, A0.w, A1.x, A1.y, A1.z, A1.w,
                              A2.x, A2.y, A2.z, A2.w};
        const float vb[12] = {B0.x, B0.y, B0.z, B0.w, B1.x, B1.y, B1.z, B1.w,
                              B2.x, B2.y, B2.z, B2.w};

        float o[PX];
#pragma unroll
        for (int j = 0; j < PX; ++j) {
            const float t = fmaf(u1[j], va[M + j + 1], u0[j] * va[M + j]);
            const float s = fmaf(u1[j], vb[M + j + 1], u0[j] * vb[M + j]);
            o[j] = fmaf(wbot, s, wtop * t);
        }
        float4* dst = &obase[y * (WW / 4) + c * 2];
        __stcs(dst,     make_float4(o[0], o[1], o[2], o[3]));
        __stcs(dst + 1, make_float4(o[4], o[5], o[6], o[7]));
    }
}

__global__ __launch_bounds__(256) void translate_kernel(
    const float* __restrict__ img,
    const float* __restrict__ dx,
    const float* __restrict__ dy,
    float* __restrict__ out)
{
    __shared__ __align__(16) float sdata[SROWS * WW];   // 17 KB
    __shared__ __align__(8) unsigned long long mbar;

    const int imgIdx = blockIdx.y;
    const float tx = __ldg(dx + imgIdx);
    const float ty = __ldg(dy + imgIdx);

    const int yb = blockIdx.x * RPB;
    const int y0_min = (int)floorf((float)yb - ty);
    const int g0 = min(max(y0_min, 0), HH - 1);
    int g1 = min(y0_min + SROWS - 1, HH - 1);
    g1 = max(g1, g0);
    const int cnt = g1 - g0 + 1;
    const int lo = g0 - y0_min;          // loaded span in smem-row units
    const int hi = g1 - y0_min;

    const float* base = img + (size_t)imgIdx * (HH * WW);
    const int tid = threadIdx.x + threadIdx.y * TPR;

    if (tid == 0) {
        const uint32_t mb = smem_u32(&mbar);
        asm volatile("mbarrier.init.shared::cta.b64 [%0], 1;" :: "r"(mb) : "memory");
        asm volatile("fence.proxy.async.shared::cta;" ::: "memory");
    }
    __syncthreads();

    if (tid == 0) {
        const uint32_t mb    = smem_u32(&mbar);
        const uint32_t bytes = (uint32_t)cnt * (WW * 4);
        const uint32_t dstp  = smem_u32(sdata + lo * WW);
        const float*   srcp  = base + (size_t)g0 * WW;
        asm volatile("mbarrier.arrive.expect_tx.shared::cta.b64 _, [%0], %1;"
                     :: "r"(mb), "r"(bytes) : "memory");
        asm volatile(
            "cp.async.bulk.shared::cluster.global.mbarrier::complete_tx::bytes "
            "[%0], [%1], %2, [%3];"
            :: "r"(dstp), "l"(srcp), "r"(bytes), "r"(mb) : "memory");
    }

    // ---- column prologue (independent of the TMA; overlaps the copy) ----
    const int c = threadIdx.x;                       // 0..31
    const int x = c * PX;
    const int yBase = yb + threadIdx.y * RPT;

    const int   x0 = (int)floorf((float)x - tx);
    const int   m  = x0 & 3;                         // uniform per image
    const int   cbase = x0 - m;

    const int qa = min(max(cbase,     0), WW - 4) >> 2;
    const int qb = min(max(cbase + 4, 0), WW - 4) >> 2;
    const int qc = min(max(cbase + 8, 0), WW - 4) >> 2;

    float u0[PX], u1[PX];
#pragma unroll
    for (int j = 0; j < PX; ++j) {
        const float wx = ((float)(x + j) - tx) - (float)(x0 + j);
        const bool v0 = (unsigned)(x0 + j)     < (unsigned)WW;
        const bool v1 = (unsigned)(x0 + j + 1) < (unsigned)WW;
        u0[j] = v0 ? (1.0f - wx) : 0.0f;
        u1[j] = v1 ? wx          : 0.0f;
    }

    // ---- wait for the staged rows, then compute from SMEM ----
    mbar_wait_parity0(smem_u32(&mbar));

    float4* obase = (float4*)(out + (size_t)imgIdx * (HH * WW));

    switch (m) {
    case 0:  run_rows<0>(sdata, obase, yBase, c, qa, qb, qc, lo, hi, y0_min, u0, u1, ty); break;
    case 1:  run_rows<1>(sdata, obase, yBase, c, qa, qb, qc, lo, hi, y0_min, u0, u1, ty); break;
    case 2:  run_rows<2>(sdata, obase, yBase, c, qa, qb, qc, lo, hi, y0_min, u0, u1, ty); break;
    default: run_rows<3>(sdata, obase, yBase, c, qa, qb, qc, lo, hi, y0_min, u0, u1, ty); break;
    }
}

extern "C" void kernel_launch(void* const* d_in, const int* in_sizes, int n_in,
                              void* d_out, int out_size) {
    const float* images = (const float*)d_in[0];
    const float* dx     = (const float*)d_in[1];
    const float* dy     = (const float*)d_in[2];
    // d_in[3] is winsize (unused by the math)
    float* out = (float*)d_out;

    const int n_images = in_sizes[1];  // B*T

    dim3 block(TPR, WPB);              // 32 x 8 = 256 threads
    dim3 grid(HH / RPB, n_images);     // 16 x 1024
    translate_kernel<<<grid, block>>>(images, dx, dy, out);
}

// round 12
// speedup vs baseline: 1.1057x; 1.1057x over previous
#include <cuda_runtime.h>

// TranslateCube: out(y,x) = bilinear(in, y - ty, x - tx), zero fill.
// [B*T, 256, 256] fp32; (tx, ty) constant per image.
//
// R6-R10 plateau diagnosis: L1tex wavefronts were the binder (L1 72-74%
// while DRAM pinned ~67%). Old layout had 32B lane stride -> every 128-bit
// memory op touched ~8 cache lines. New layout: thread c owns two 4-px quads
// at x=4c and x=4c+128 -> chunk index = c + const -> 16B lane stride, every
// LDG.128/STG.128 fully coalesced (4-5 lines). The +128 offset preserves
// fractional weights and misalignment M, so the column prologue is shared.

#define HH 256
#define WW 256
#define TPR 32               // threads per row (one warp = one full row)
#define WPB 8                // warps per block
#define RPT 2                // rows per thread
#define RPB (WPB * RPT)      // 16 rows per block

// Interpolate one 4-px quad from an 8-float window (two float4 chunks),
// with window offset M (uniform per image).
template <int M>
__device__ __forceinline__ float4 quad(
    const float4 A0, const float4 A1,   // top row chunks
    const float4 B0, const float4 B1,   // bottom row chunks
    const float* __restrict__ u0, const float* __restrict__ u1,
    float wtop, float wbot)
{
    const float va[8] = {A0.x, A0.y, A0.z, A0.w, A1.x, A1.y, A1.z, A1.w};
    const float vb[8] = {B0.x, B0.y, B0.z, B0.w, B1.x, B1.y, B1.z, B1.w};
    float o[4];
#pragma unroll
    for (int j = 0; j < 4; ++j) {
        const float t = fmaf(u1[j], va[M + j + 1], u0[j] * va[M + j]);
        const float s = fmaf(u1[j], vb[M + j + 1], u0[j] * vb[M + j]);
        o[j] = fmaf(wbot, s, wtop * t);
    }
    return make_float4(o[0], o[1], o[2], o[3]);
}

template <int M>
__device__ __forceinline__ void run_rows(
    const float* __restrict__ base, float4* __restrict__ obase,
    int yBase, int c, int ca0, int ca1, int cb0, int cb1,
    const float* __restrict__ u0a, const float* __restrict__ u1a,
    const float* __restrict__ u0b, const float* __restrict__ u1b, float ty)
{
#pragma unroll
    for (int r = 0; r < RPT; ++r) {
        const int y = yBase + r;
        const float sy  = (float)y - ty;
        const float y0f = floorf(sy);
        const float wy  = sy - y0f;
        const int   y0  = (int)y0f;
        const float wtop = ((unsigned)y0       < (unsigned)HH) ? (1.0f - wy) : 0.0f;
        const float wbot = ((unsigned)(y0 + 1) < (unsigned)HH) ? wy          : 0.0f;
        const int y0c = min(max(y0,     0), HH - 1);
        const int y1c = min(max(y0 + 1, 0), HH - 1);

        const float4* r0 = (const float4*)(base + (size_t)y0c * WW);
        const float4* r1 = (const float4*)(base + (size_t)y1c * WW);

        // 8 independent, lane-contiguous LDG.128
        const float4 A0 = __ldg(r0 + ca0), A1 = __ldg(r0 + ca1);
        const float4 A2 = __ldg(r0 + cb0), A3 = __ldg(r0 + cb1);
        const float4 B0 = __ldg(r1 + ca0), B1 = __ldg(r1 + ca1);
        const float4 B2 = __ldg(r1 + cb0), B3 = __ldg(r1 + cb1);

        const float4 oA = quad<M>(A0, A1, B0, B1, u0a, u1a, wtop, wbot);
        const float4 oB = quad<M>(A2, A3, B2, B3, u0b, u1b, wtop, wbot);

        float4* dst = &obase[y * (WW / 4)];
        __stcs(dst + c,      oA);
        __stcs(dst + c + 32, oB);
    }
}

__global__ __launch_bounds__(256) void translate_kernel(
    const float* __restrict__ img,
    const float* __restrict__ dx,
    const float* __restrict__ dy,
    float* __restrict__ out)
{
    const int imgIdx = blockIdx.y;
    const float tx = __ldg(dx + imgIdx);
    const float ty = __ldg(dy + imgIdx);

    const int c = threadIdx.x;                   // 0..31
    const int xa = c * 4;                        // quad A base column
    const int xb = xa + 128;                     // quad B base column
    const int yBase = blockIdx.x * RPB + threadIdx.y * RPT;

    const int x0a = (int)floorf((float)xa - tx);
    const int x0b = x0a + 128;                   // integer offset preserves frac
    const int m   = x0a & 3;                     // uniform per image
    const int qbase = (x0a - m) >> 2;

    // Clamped, always-in-bounds chunk indices; OOB pixels get zero weight.
    const int ca0 = min(max(qbase,      0), WW / 4 - 1);
    const int ca1 = min(max(qbase + 1,  0), WW / 4 - 1);
    const int cb0 = min(max(qbase + 32, 0), WW / 4 - 1);
    const int cb1 = min(max(qbase + 33, 0), WW / 4 - 1);

    // Horizontal weights (reference fp32 expressions) with validity folded in.
    float u0a[4], u1a[4], u0b[4], u1b[4];
#pragma unroll
    for (int j = 0; j < 4; ++j) {
        const float wxa = ((float)(xa + j) - tx) - (float)(x0a + j);
        u0a[j] = ((unsigned)(x0a + j)     < (unsigned)WW) ? (1.0f - wxa) : 0.0f;
        u1a[j] = ((unsigned)(x0a + j + 1) < (unsigned)WW) ? wxa          : 0.0f;
        const float wxb = ((float)(xb + j) - tx) - (float)(x0b + j);
        u0b[j] = ((unsigned)(x0b + j)     < (unsigned)WW) ? (1.0f - wxb) : 0.0f;
        u1b[j] = ((unsigned)(x0b + j + 1) < (unsigned)WW) ? wxb          : 0.0f;
    }

    const float* base  = img + (size_t)imgIdx * (HH * WW);
    float4*      obase = (float4*)(out + (size_t)imgIdx * (HH * WW));

    switch (m) {
    case 0:  run_rows<0>(base, obase, yBase, c, ca0, ca1, cb0, cb1, u0a, u1a, u0b, u1b, ty); break;
    case 1:  run_rows<1>(base, obase, yBase, c, ca0, ca1, cb0, cb1, u0a, u1a, u0b, u1b, ty); break;
    case 2:  run_rows<2>(base, obase, yBase, c, ca0, ca1, cb0, cb1, u0a, u1a, u0b, u1b, ty); break;
    default: run_rows<3>(base, obase, yBase, c, ca0, ca1, cb0, cb1, u0a, u1a, u0b, u1b, ty); break;
    }
}

extern "C" void kernel_launch(void* const* d_in, const int* in_sizes, int n_in,
                              void* d_out, int out_size) {
    const float* images = (const float*)d_in[0];
    const float* dx     = (const float*)d_in[1];
    const float* dy     = (const float*)d_in[2];
    // d_in[3] is winsize (unused by the math)
    float* out = (float*)d_out;

    const int n_images = in_sizes[1];  // B*T

    dim3 block(TPR, WPB);              // 32 x 8 = 256 threads
    dim3 grid(HH / RPB, n_images);     // 16 x 1024
    translate_kernel<<<grid, block>>>(images, dx, dy, out);
}

// round 13
// speedup vs baseline: 1.1142x; 1.0076x over previous
#include <cuda_runtime.h>

// TranslateCube: out(y,x) = bilinear(in, y - ty, x - tx), zero fill.
// [B*T, 256, 256] fp32; (tx, ty) constant per image.
//
// R12 (coalesced two-quad layout) dropped L1 to 48% but occ fell to 42%
// (56 regs, 4 blocks/SM) leaving the kernel DRAM-latency bound. This round:
// same layout + __launch_bounds__(256,5) -> regs<=48 -> 5 blocks/SM. The
// 8-load batch may split into two independent 4-load quad batches; with
// cheap (fully coalesced) wavefronts the +25% warps should net out positive.

#define HH 256
#define WW 256
#define TPR 32               // threads per row (one warp = one full row)
#define WPB 8                // warps per block
#define RPT 2                // rows per thread
#define RPB (WPB * RPT)      // 16 rows per block

template <int M>
__device__ __forceinline__ float4 quad(
    const float4 A0, const float4 A1,   // top row chunks
    const float4 B0, const float4 B1,   // bottom row chunks
    const float* __restrict__ u0, const float* __restrict__ u1,
    float wtop, float wbot)
{
    const float va[8] = {A0.x, A0.y, A0.z, A0.w, A1.x, A1.y, A1.z, A1.w};
    const float vb[8] = {B0.x, B0.y, B0.z, B0.w, B1.x, B1.y, B1.z, B1.w};
    float o[4];
#pragma unroll
    for (int j = 0; j < 4; ++j) {
        const float t = fmaf(u1[j], va[M + j + 1], u0[j] * va[M + j]);
        const float s = fmaf(u1[j], vb[M + j + 1], u0[j] * vb[M + j]);
        o[j] = fmaf(wbot, s, wtop * t);
    }
    return make_float4(o[0], o[1], o[2], o[3]);
}

template <int M>
__device__ __forceinline__ void run_rows(
    const float* __restrict__ base, float4* __restrict__ obase,
    int yBase, int c, int ca0, int ca1, int cb0, int cb1,
    const float* __restrict__ u0a, const float* __restrict__ u1a,
    const float* __restrict__ u0b, const float* __restrict__ u1b, float ty)
{
#pragma unroll
    for (int r = 0; r < RPT; ++r) {
        const int y = yBase + r;
        const float sy  = (float)y - ty;
        const float y0f = floorf(sy);
        const float wy  = sy - y0f;
        const int   y0  = (int)y0f;
        const float wtop = ((unsigned)y0       < (unsigned)HH) ? (1.0f - wy) : 0.0f;
        const float wbot = ((unsigned)(y0 + 1) < (unsigned)HH) ? wy          : 0.0f;
        const int y0c = min(max(y0,     0), HH - 1);
        const int y1c = min(max(y0 + 1, 0), HH - 1);

        const float4* r0 = (const float4*)(base + (size_t)y0c * WW);
        const float4* r1 = (const float4*)(base + (size_t)y1c * WW);

        // 8 independent, lane-contiguous LDG.128
        const float4 A0 = __ldg(r0 + ca0), A1 = __ldg(r0 + ca1);
        const float4 A2 = __ldg(r0 + cb0), A3 = __ldg(r0 + cb1);
        const float4 B0 = __ldg(r1 + ca0), B1 = __ldg(r1 + ca1);
        const float4 B2 = __ldg(r1 + cb0), B3 = __ldg(r1 + cb1);

        const float4 oA = quad<M>(A0, A1, B0, B1, u0a, u1a, wtop, wbot);
        const float4 oB = quad<M>(A2, A3, B2, B3, u0b, u1b, wtop, wbot);

        float4* dst = &obase[y * (WW / 4)];
        __stcs(dst + c,      oA);
        __stcs(dst + c + 32, oB);
    }
}

__global__ __launch_bounds__(256, 5) void translate_kernel(
    const float* __restrict__ img,
    const float* __restrict__ dx,
    const float* __restrict__ dy,
    float* __restrict__ out)
{
    const int imgIdx = blockIdx.y;
    const float tx = __ldg(dx + imgIdx);
    const float ty = __ldg(dy + imgIdx);

    const int c = threadIdx.x;                   // 0..31
    const int xa = c * 4;                        // quad A base column
    const int xb = xa + 128;                     // quad B base column
    const int yBase = blockIdx.x * RPB + threadIdx.y * RPT;

    const int x0a = (int)floorf((float)xa - tx);
    const int x0b = x0a + 128;                   // integer offset preserves frac
    const int m   = x0a & 3;                     // uniform per image
    const int qbase = (x0a - m) >> 2;

    // Clamped, always-in-bounds chunk indices; OOB pixels get zero weight.
    const int ca0 = min(max(qbase,      0), WW / 4 - 1);
    const int ca1 = min(max(qbase + 1,  0), WW / 4 - 1);
    const int cb0 = min(max(qbase + 32, 0), WW / 4 - 1);
    const int cb1 = min(max(qbase + 33, 0), WW / 4 - 1);

    // Horizontal weights (reference fp32 expressions) with validity folded in.
    float u0a[4], u1a[4], u0b[4], u1b[4];
#pragma unroll
    for (int j = 0; j < 4; ++j) {
        const float wxa = ((float)(xa + j) - tx) - (float)(x0a + j);
        u0a[j] = ((unsigned)(x0a + j)     < (unsigned)WW) ? (1.0f - wxa) : 0.0f;
        u1a[j] = ((unsigned)(x0a + j + 1) < (unsigned)WW) ? wxa          : 0.0f;
        const float wxb = ((float)(xb + j) - tx) - (float)(x0b + j);
        u0b[j] = ((unsigned)(x0b + j)     < (unsigned)WW) ? (1.0f - wxb) : 0.0f;
        u1b[j] = ((unsigned)(x0b + j + 1) < (unsigned)WW) ? wxb          : 0.0f;
    }

    const float* base  = img + (size_t)imgIdx * (HH * WW);
    float4*      obase = (float4*)(out + (size_t)imgIdx * (HH * WW));

    switch (m) {
    case 0:  run_rows<0>(base, obase, yBase, c, ca0, ca1, cb0, cb1, u0a, u1a, u0b, u1b, ty); break;
    case 1:  run_rows<1>(base, obase, yBase, c, ca0, ca1, cb0, cb1, u0a, u1a, u0b, u1b, ty); break;
    case 2:  run_rows<2>(base, obase, yBase, c, ca0, ca1, cb0, cb1, u0a, u1a, u0b, u1b, ty); break;
    default: run_rows<3>(base, obase, yBase, c, ca0, ca1, cb0, cb1, u0a, u1a, u0b, u1b, ty); break;
    }
}

extern "C" void kernel_launch(void* const* d_in, const int* in_sizes, int n_in,
                              void* d_out, int out_size) {
    const float* images = (const float*)d_in[0];
    const float* dx     = (const float*)d_in[1];
    const float* dy     = (const float*)d_in[2];
    // d_in[3] is winsize (unused by the math)
    float* out = (float*)d_out;

    const int n_images = in_sizes[1];  // B*T

    dim3 block(TPR, WPB);              // 32 x 8 = 256 threads
    dim3 grid(HH / RPB, n_images);     // 16 x 1024
    translate_kernel<<<grid, block>>>(images, dx, dy, out);
}

// round 14
// speedup vs baseline: 1.1875x; 1.0658x over previous
#include <cuda_runtime.h>
#include <cstdint>

// TranslateCube: out(y,x) = bilinear(in, y - ty, x - tx), zero fill.
// [B*T, 256, 256] fp32; (tx, ty) constant per image.
//
// R6-R13 lesson: synchronous LDG caps at ~5.5 TB/s because outstanding DRAM
// bytes are register-file limited (occ x MLP conserved across 4 configs).
// This round: cp.async (LDGSTS) double-buffered tile pipeline — zero register
// payload for reads. One block = half an image (8 tiles x 16 rows); tile t+1
// is prefetched into the alternate smem buffer while tile t computes.
// Compute body = R13's coalesced two-quad form, reading smem instead of gmem.

#define HH 256
#define WW 256
#define TPR 32               // threads in x (one warp = one row slice)
#define WPB 8                // warps per block
#define RPT 2                // rows per thread per tile
#define TROWS 16             // output rows per tile
#define SROWS 17             // staged input rows per tile
#define HALF 128             // output rows per block
#define NT (HALF / TROWS)    // 8 tiles per block

__device__ __forceinline__ uint32_t smem_u32(const void* p) {
    return (uint32_t)__cvta_generic_to_shared(p);
}

struct TileInfo { int y0_min, g0, lo, hi, cnt; };

__device__ __forceinline__ TileInfo tile_info(int yb, float ty) {
    TileInfo t;
    t.y0_min = (int)floorf((float)yb - ty);
    t.g0 = min(max(t.y0_min, 0), HH - 1);
    int g1 = max(min(t.y0_min + SROWS - 1, HH - 1), t.g0);
    // smem span; clamped so writes/reads always stay inside the buffer even
    // for pathological shifts (weights are zero there anyway).
    t.lo = min(max(t.g0 - t.y0_min, 0), SROWS - 1);
    t.hi = min(max(g1   - t.y0_min, t.lo), SROWS - 1);
    t.cnt = min(g1 - t.g0 + 1, SROWS - t.lo);
    return t;
}

__device__ __forceinline__ void prefetch_tile(
    float* __restrict__ sbuf, const float* __restrict__ base,
    const TileInfo ti, int tid)
{
    const uint32_t bytes = (uint32_t)ti.cnt * (WW * 4);
    const char* src = (const char*)(base + (size_t)ti.g0 * WW);
    const uint32_t dst = smem_u32(sbuf + ti.lo * WW);
#pragma unroll
    for (int it = 0; it < (SROWS * WW * 4 + 4095) / 4096; ++it) {
        const uint32_t off = (uint32_t)tid * 16 + (uint32_t)it * 4096;
        if (off < bytes) {
            asm volatile("cp.async.cg.shared.global [%0], [%1], 16;"
                         :: "r"(dst + off), "l"(src + off) : "memory");
        }
    }
    asm volatile("cp.async.commit_group;" ::: "memory");
}

template <int M>
__device__ __forceinline__ float4 quad(
    const float4 A0, const float4 A1, const float4 B0, const float4 B1,
    const float* __restrict__ u0, const float* __restrict__ u1,
    float wtop, float wbot)
{
    const float va[8] = {A0.x, A0.y, A0.z, A0.w, A1.x, A1.y, A1.z, A1.w};
    const float vb[8] = {B0.x, B0.y, B0.z, B0.w, B1.x, B1.y, B1.z, B1.w};
    float o[4];
#pragma unroll
    for (int j = 0; j < 4; ++j) {
        const float t = fmaf(u1[j], va[M + j + 1], u0[j] * va[M + j]);
        const float s = fmaf(u1[j], vb[M + j + 1], u0[j] * vb[M + j]);
        o[j] = fmaf(wbot, s, wtop * t);
    }
    return make_float4(o[0], o[1], o[2], o[3]);
}

template <int M>
__device__ __forceinline__ void pipeline(
    const float* __restrict__ base, float4* __restrict__ obase,
    float* __restrict__ s0, float* __restrict__ s1,
    int yStart, int c, int tid,
    int ca0, int ca1, int cb0, int cb1,
    const float* __restrict__ u0a, const float* __restrict__ u1a,
    const float* __restrict__ u0b, const float* __restrict__ u1b, float ty)
{
    prefetch_tile(s0, base, tile_info(yStart, ty), tid);

    for (int t = 0; t < NT; ++t) {
        float* sc = (t & 1) ? s1 : s0;
        const TileInfo cur = tile_info(yStart + t * TROWS, ty);

        if (t + 1 < NT) {
            prefetch_tile((t & 1) ? s0 : s1, base,
                          tile_info(yStart + (t + 1) * TROWS, ty), tid);
            asm volatile("cp.async.wait_group 1;" ::: "memory");
        } else {
            asm volatile("cp.async.wait_group 0;" ::: "memory");
        }
        __syncthreads();

        const int yBase = yStart + t * TROWS + threadIdx.y * RPT;
#pragma unroll
        for (int r = 0; r < RPT; ++r) {
            const int y = yBase + r;
            const float sy  = (float)y - ty;
            const float y0f = floorf(sy);
            const float wy  = sy - y0f;
            const int   y0  = (int)y0f;
            const float wtop = ((unsigned)y0       < (unsigned)HH) ? (1.0f - wy) : 0.0f;
            const float wbot = ((unsigned)(y0 + 1) < (unsigned)HH) ? wy          : 0.0f;
            const int i0 = min(max(y0     - cur.y0_min, cur.lo), cur.hi);
            const int i1 = min(max(y0 + 1 - cur.y0_min, cur.lo), cur.hi);

            const float4* r0 = (const float4*)(sc + i0 * WW);
            const float4* r1 = (const float4*)(sc + i1 * WW);
            const float4 A0 = r0[ca0], A1 = r0[ca1], A2 = r0[cb0], A3 = r0[cb1];
            const float4 B0 = r1[ca0], B1 = r1[ca1], B2 = r1[cb0], B3 = r1[cb1];

            const float4 oA = quad<M>(A0, A1, B0, B1, u0a, u1a, wtop, wbot);
            const float4 oB = quad<M>(A2, A3, B2, B3, u0b, u1b, wtop, wbot);

            float4* dst = &obase[y * (WW / 4)];
            __stcs(dst + c,      oA);
            __stcs(dst + c + 32, oB);
        }
        __syncthreads();   // compute done before buffer is overwritten
    }
}

__global__ __launch_bounds__(256, 5) void translate_kernel(
    const float* __restrict__ img,
    const float* __restrict__ dx,
    const float* __restrict__ dy,
    float* __restrict__ out)
{
    __shared__ __align__(16) float sbuf[2][SROWS * WW];   // 2 x 17 KB

    const int bx = blockIdx.x;
    const int imgIdx = bx >> 1;
    const int yStart = (bx & 1) * HALF;

    const float tx = __ldg(dx + imgIdx);
    const float ty = __ldg(dy + imgIdx);

    const int c  = threadIdx.x;                  // 0..31
    const int xa = c * 4;
    const int xb = xa + 128;
    const int tid = threadIdx.y * TPR + threadIdx.x;

    const int x0a = (int)floorf((float)xa - tx);
    const int x0b = x0a + 128;
    const int m   = x0a & 3;                     // uniform per image
    const int qbase = (x0a - m) >> 2;

    const int ca0 = min(max(qbase,      0), WW / 4 - 1);
    const int ca1 = min(max(qbase + 1,  0), WW / 4 - 1);
    const int cb0 = min(max(qbase + 32, 0), WW / 4 - 1);
    const int cb1 = min(max(qbase + 33, 0), WW / 4 - 1);

    float u0a[4], u1a[4], u0b[4], u1b[4];
#pragma unroll
    for (int j = 0; j < 4; ++j) {
        const float wxa = ((float)(xa + j) - tx) - (float)(x0a + j);
        u0a[j] = ((unsigned)(x0a + j)     < (unsigned)WW) ? (1.0f - wxa) : 0.0f;
        u1a[j] = ((unsigned)(x0a + j + 1) < (unsigned)WW) ? wxa          : 0.0f;
        const float wxb = ((float)(xb + j) - tx) - (float)(x0b + j);
        u0b[j] = ((unsigned)(x0b + j)     < (unsigned)WW) ? (1.0f - wxb) : 0.0f;
        u1b[j] = ((unsigned)(x0b + j + 1) < (unsigned)WW) ? wxb          : 0.0f;
    }

    const float* base  = img + (size_t)imgIdx * (HH * WW);
    float4*      obase = (float4*)(out + (size_t)imgIdx * (HH * WW));

    switch (m) {
    case 0:  pipeline<0>(base, obase, sbuf[0], sbuf[1], yStart, c, tid,
                         ca0, ca1, cb0, cb1, u0a, u1a, u0b, u1b, ty); break;
    case 1:  pipeline<1>(base, obase, sbuf[0], sbuf[1], yStart, c, tid,
                         ca0, ca1, cb0, cb1, u0a, u1a, u0b, u1b, ty); break;
    case 2:  pipeline<2>(base, obase, sbuf[0], sbuf[1], yStart, c, tid,
                         ca0, ca1, cb0, cb1, u0a, u1a, u0b, u1b, ty); break;
    default: pipeline<3>(base, obase, sbuf[0], sbuf[1], yStart, c, tid,
                         ca0, ca1, cb0, cb1, u0a, u1a, u0b, u1b, ty); break;
    }
}

extern "C" void kernel_launch(void* const* d_in, const int* in_sizes, int n_in,
                              void* d_out, int out_size) {
    const float* images = (const float*)d_in[0];
    const float* dx     = (const float*)d_in[1];
    const float* dy     = (const float*)d_in[2];
    // d_in[3] is winsize (unused by the math)
    float* out = (float*)d_out;

    const int n_images = in_sizes[1];  // B*T

    dim3 block(TPR, WPB);              // 32 x 8 = 256 threads
    dim3 grid(2 * n_images);           // one block per half-image
    translate_kernel<<<grid, block>>>(images, dx, dy, out);
}

// round 15
// speedup vs baseline: 1.1937x; 1.0052x over previous
#include <cuda_runtime.h>
#include <cstdint>

// TranslateCube: out(y,x) = bilinear(in, y - ty, x - tx), zero fill.
// [B*T, 256, 256] fp32; (tx, ty) constant per image.
//
// R14 (cp.async double-buffer) reached DRAM 75%. This round deepens the
// pipeline: 4 buffers x 8-row tiles (9KB each), prefetch distance 3, ONE
// __syncthreads per tile (the 4-buffer rotation makes the trailing sync
// redundant: prefetch t+3 targets the buffer last read at t-1, whose compute
// finished before this iteration's barrier). Empty commit_groups keep the
// wait_group counting uniform through the tail.

#define HH 256
#define WW 256
#define TPR 32               // threads in x
#define WPB 8                // warps per block (threadIdx.y = row in tile)
#define TROWS 8              // output rows per tile
#define SROWS 9              // staged input rows per tile
#define NBUF 4
#define HALF 128             // output rows per block
#define NT (HALF / TROWS)    // 16 tiles per block
#define PDIST 3              // prefetch distance (tiles)

__device__ __forceinline__ uint32_t smem_u32(const void* p) {
    return (uint32_t)__cvta_generic_to_shared(p);
}

struct TileInfo { int y0_min, g0, lo, hi, cnt; };

__device__ __forceinline__ TileInfo tile_info(int yb, float ty) {
    TileInfo t;
    t.y0_min = (int)floorf((float)yb - ty);
    t.g0 = min(max(t.y0_min, 0), HH - 1);
    int g1 = max(min(t.y0_min + SROWS - 1, HH - 1), t.g0);
    t.lo = min(max(t.g0 - t.y0_min, 0), SROWS - 1);
    t.hi = min(max(g1   - t.y0_min, t.lo), SROWS - 1);
    t.cnt = min(g1 - t.g0 + 1, SROWS - t.lo);
    return t;
}

__device__ __forceinline__ void prefetch_tile(
    float* __restrict__ sbuf, const float* __restrict__ base,
    const TileInfo ti, int tid)
{
    const uint32_t bytes = (uint32_t)ti.cnt * (WW * 4);
    const char* src = (const char*)(base + (size_t)ti.g0 * WW);
    const uint32_t dst = smem_u32(sbuf + ti.lo * WW);
#pragma unroll
    for (int it = 0; it < (SROWS * WW * 4 + 4095) / 4096; ++it) {
        const uint32_t off = (uint32_t)tid * 16 + (uint32_t)it * 4096;
        if (off < bytes) {
            asm volatile("cp.async.cg.shared.global [%0], [%1], 16;"
                         :: "r"(dst + off), "l"(src + off) : "memory");
        }
    }
    asm volatile("cp.async.commit_group;" ::: "memory");
}

template <int M>
__device__ __forceinline__ float4 quad(
    const float4 A0, const float4 A1, const float4 B0, const float4 B1,
    const float* __restrict__ u0, const float* __restrict__ u1,
    float wtop, float wbot)
{
    const float va[8] = {A0.x, A0.y, A0.z, A0.w, A1.x, A1.y, A1.z, A1.w};
    const float vb[8] = {B0.x, B0.y, B0.z, B0.w, B1.x, B1.y, B1.z, B1.w};
    float o[4];
#pragma unroll
    for (int j = 0; j < 4; ++j) {
        const float t = fmaf(u1[j], va[M + j + 1], u0[j] * va[M + j]);
        const float s = fmaf(u1[j], vb[M + j + 1], u0[j] * vb[M + j]);
        o[j] = fmaf(wbot, s, wtop * t);
    }
    return make_float4(o[0], o[1], o[2], o[3]);
}

template <int M>
__device__ __forceinline__ void pipeline(
    const float* __restrict__ base, float4* __restrict__ obase,
    float* __restrict__ sbuf,                 // NBUF * SROWS * WW floats
    int yStart, int c, int tid,
    int ca0, int ca1, int cb0, int cb1,
    const float* __restrict__ u0a, const float* __restrict__ u1a,
    const float* __restrict__ u0b, const float* __restrict__ u1b, float ty)
{
#pragma unroll
    for (int p = 0; p < PDIST; ++p)
        prefetch_tile(sbuf + p * (SROWS * WW), base,
                      tile_info(yStart + p * TROWS, ty), tid);

    for (int t = 0; t < NT; ++t) {
        const TileInfo cur = tile_info(yStart + t * TROWS, ty);
        float* sc = sbuf + (t & (NBUF - 1)) * (SROWS * WW);

        asm volatile("cp.async.wait_group %0;" :: "n"(PDIST - 1) : "memory");
        __syncthreads();   // tile t visible to all; all finished tile t-1

        // one row per thread per tile
        const int y = yStart + t * TROWS + threadIdx.y;
        {
            const float sy  = (float)y - ty;
            const float y0f = floorf(sy);
            const float wy  = sy - y0f;
            const int   y0  = (int)y0f;
            const float wtop = ((unsigned)y0       < (unsigned)HH) ? (1.0f - wy) : 0.0f;
            const float wbot = ((unsigned)(y0 + 1) < (unsigned)HH) ? wy          : 0.0f;
            const int i0 = min(max(y0     - cur.y0_min, cur.lo), cur.hi);
            const int i1 = min(max(y0 + 1 - cur.y0_min, cur.lo), cur.hi);

            const float4* r0 = (const float4*)(sc + i0 * WW);
            const float4* r1 = (const float4*)(sc + i1 * WW);
            const float4 A0 = r0[ca0], A1 = r0[ca1], A2 = r0[cb0], A3 = r0[cb1];
            const float4 B0 = r1[ca0], B1 = r1[ca1], B2 = r1[cb0], B3 = r1[cb1];

            const float4 oA = quad<M>(A0, A1, B0, B1, u0a, u1a, wtop, wbot);
            const float4 oB = quad<M>(A2, A3, B2, B3, u0b, u1b, wtop, wbot);

            float4* dst = &obase[y * (WW / 4)];
            __stcs(dst + c,      oA);
            __stcs(dst + c + 32, oB);
        }

        // Prefetch tile t+PDIST into the buffer last read at tile t-1
        // (safe: its readers all passed this iteration's barrier).
        if (t + PDIST < NT) {
            prefetch_tile(sbuf + ((t + PDIST) & (NBUF - 1)) * (SROWS * WW),
                          base, tile_info(yStart + (t + PDIST) * TROWS, ty), tid);
        } else {
            asm volatile("cp.async.commit_group;" ::: "memory");  // empty group
        }
    }
}

__global__ __launch_bounds__(256, 5) void translate_kernel(
    const float* __restrict__ img,
    const float* __restrict__ dx,
    const float* __restrict__ dy,
    float* __restrict__ out)
{
    __shared__ __align__(16) float sbuf[NBUF * SROWS * WW];   // 36 KB

    const int bx = blockIdx.x;
    const int imgIdx = bx >> 1;
    const int yStart = (bx & 1) * HALF;

    const float tx = __ldg(dx + imgIdx);
    const float ty = __ldg(dy + imgIdx);

    const int c  = threadIdx.x;                  // 0..31
    const int xa = c * 4;
    const int xb = xa + 128;
    const int tid = threadIdx.y * TPR + threadIdx.x;

    const int x0a = (int)floorf((float)xa - tx);
    const int x0b = x0a + 128;
    const int m   = x0a & 3;                     // uniform per image
    const int qbase = (x0a - m) >> 2;

    const int ca0 = min(max(qbase,      0), WW / 4 - 1);
    const int ca1 = min(max(qbase + 1,  0), WW / 4 - 1);
    const int cb0 = min(max(qbase + 32, 0), WW / 4 - 1);
    const int cb1 = min(max(qbase + 33, 0), WW / 4 - 1);

    float u0a[4], u1a[4], u0b[4], u1b[4];
#pragma unroll
    for (int j = 0; j < 4; ++j) {
        const float wxa = ((float)(xa + j) - tx) - (float)(x0a + j);
        u0a[j] = ((unsigned)(x0a + j)     < (unsigned)WW) ? (1.0f - wxa) : 0.0f;
        u1a[j] = ((unsigned)(x0a + j + 1) < (unsigned)WW) ? wxa          : 0.0f;
        const float wxb = ((float)(xb + j) - tx) - (float)(x0b + j);
        u0b[j] = ((unsigned)(x0b + j)     < (unsigned)WW) ? (1.0f - wxb) : 0.0f;
        u1b[j] = ((unsigned)(x0b + j + 1) < (unsigned)WW) ? wxb          : 0.0f;
    }

    const float* base  = img + (size_t)imgIdx * (HH * WW);
    float4*      obase = (float4*)(out + (size_t)imgIdx * (HH * WW));

    switch (m) {
    case 0:  pipeline<0>(base, obase, sbuf, yStart, c, tid,
                         ca0, ca1, cb0, cb1, u0a, u1a, u0b, u1b, ty); break;
    case 1:  pipeline<1>(base, obase, sbuf, yStart, c, tid,
                         ca0, ca1, cb0, cb1, u0a, u1a, u0b, u1b, ty); break;
    case 2:  pipeline<2>(base, obase, sbuf, yStart, c, tid,
                         ca0, ca1, cb0, cb1, u0a, u1a, u0b, u1b, ty); break;
    default: pipeline<3>(base, obase, sbuf, yStart, c, tid,
                         ca0, ca1, cb0, cb1, u0a, u1a, u0b, u1b, ty); break;
    }
}

extern "C" void kernel_launch(void* const* d_in, const int* in_sizes, int n_in,
                              void* d_out, int out_size) {
    const float* images = (const float*)d_in[0];
    const float* dx     = (const float*)d_in[1];
    const float* dy     = (const float*)d_in[2];
    // d_in[3] is winsize (unused by the math)
    float* out = (float*)d_out;

    const int n_images = in_sizes[1];  // B*T

    dim3 block(TPR, WPB);              // 32 x 8 = 256 threads
    dim3 grid(2 * n_images);           // one block per half-image
    translate_kernel<<<grid, block>>>(images, dx, dy, out);
}